// round 16
// baseline (speedup 1.0000x reference)
#include <cuda_runtime.h>
#include <cstdint>

#define DISP 49
#define GROUP 8
#define CPG 8
#define HH 96
#define WW 320
#define BB 2
#define EPSN 1e-5f
#define CHW (HH*WW)
#define PADE 49              // zero entries for the left pad
#define ROWB 12288           // smem size: 1 KB multiple (swizzle-closed)
#define DSTR ((CHW / 2) * 8) // byte stride between disparities for one thread

typedef unsigned long long u64;

__device__ __forceinline__ uint32_t swz(uint32_t o) {
    // XOR bits[6:4] with bits[9:7]: bijective within each full 1 KB block
    return o ^ ((o >> 3) & 0x70);
}
__device__ __forceinline__ uint32_t smem32(const void* p) {
    uint32_t r;
    asm("{ .reg .u64 t; cvta.to.shared.u64 t, %1; cvt.u32.u64 %0, t; }"
        : "=r"(r) : "l"(p));
    return r;
}
__device__ __forceinline__ u64 add2(u64 a, u64 b) {
    u64 r; asm("add.rn.f32x2 %0, %1, %2;" : "=l"(r) : "l"(a), "l"(b)); return r;
}
__device__ __forceinline__ u64 pack2(float lo, float hi) {
    u64 r; asm("mov.b64 %0, {%1, %2};" : "=l"(r) : "f"(lo), "f"(hi)); return r;
}
__device__ __forceinline__ void unpack2(u64 a, float& lo, float& hi) {
    asm("mov.b64 {%0, %1}, %2;" : "=f"(lo), "=f"(hi) : "l"(a));
}
// swz(o+16) = swz(o) ^ 16 for 32-aligned o (bit 4 of o is 0; mask +16-invariant)
__device__ __forceinline__ void lds32B(u64& a, u64& b, u64& c, u64& d, uint32_t ad) {
    asm("ld.shared.v2.u64 {%0, %1}, [%2];" : "=l"(a), "=l"(b) : "r"(ad));
    asm("ld.shared.v2.u64 {%0, %1}, [%2];" : "=l"(c), "=l"(d) : "r"(ad ^ 16u));
}
__device__ __forceinline__ void sts32B(uint32_t ad, u64 a, u64 b, u64 c, u64 d) {
    asm("st.shared.v2.u64 [%0], {%1, %2};" :: "r"(ad), "l"(a), "l"(b) : "memory");
    asm("st.shared.v2.u64 [%0], {%1, %2};" :: "r"(ad ^ 16u), "l"(c), "l"(d) : "memory");
}
// streaming store: outputs are write-once, never re-read -> evict-first
__device__ __forceinline__ void stg_cs_f2(void* p, float lo, float hi) {
    asm("st.global.cs.v2.f32 [%0], {%1, %2};" :: "l"(p), "f"(lo), "f"(hi) : "memory");
}

// Pairs 0-2 abs'd via LOP3 mask, summed packed (6 add2 + 6 LOP3); pair 3
// kept raw — abs is free via FADD |.| operand modifiers in the scalar tail.
__device__ __forceinline__ float cost8(const u64 (&xp)[4], const u64 (&wp)[4]) {
    const u64 M = 0x7fffffff7fffffffULL;
    u64 d0 = add2(xp[0], wp[0]) & M;
    u64 d1 = add2(xp[1], wp[1]) & M;
    u64 d2 = add2(xp[2], wp[2]) & M;
    u64 d3 = add2(xp[3], wp[3]);
    float tl, th, dl, dh;
    unpack2(add2(add2(d0, d1), d2), tl, th);
    unpack2(d3, dl, dh);
    return (tl + th) + (fabsf(dl) + fabsf(dh));
}

// One disparity step: 2 outputs/thread. 3-slot sliding window of NEGATED yn
// entries; slot(offset o = entry - w0) = o mod 3, DM = d mod 3 compile-time.
// abo = ybase-prefolded refill address (swz(ybase+bo) = ybase+swz(bo) since
// ybase % 1024 == 0). KO folds refill/output offsets into immediates.
// Refill issued FIRST; consumed mid-NEXT-step.
template<int DM, int KO>
__device__ __forceinline__ void step(const u64 (&xn)[2][4], u64 (&Wn)[3][4],
                                     uint32_t abo, char* op) {
    constexpr int S1 = ((1 - DM) % 3 + 3) % 3;
    constexpr int S0 = ((0 - DM) % 3 + 3) % 3;
    constexpr int SR = ((-1 - DM) % 3 + 3) % 3;

    uint32_t ad = abo - 32u * KO;
    ad ^= (ad >> 3) & 0x70;
    lds32B(Wn[SR][0], Wn[SR][1], Wn[SR][2], Wn[SR][3], ad);

    const float r1 = cost8(xn[1], Wn[S1]);
    const float r0 = cost8(xn[0], Wn[S0]);
    stg_cs_f2(op + (long long)KO * DSTR, r0, r1);
}

__global__ __launch_bounds__(160, 7)
void cost_volume_kernel(const float* __restrict__ x,
                        const float* __restrict__ y,
                        float* __restrict__ out) {
    __shared__ __align__(1024) char yns[ROWB];

    const int lx = threadIdx.x;          // owns w = 2lx, 2lx+1
    const int h = blockIdx.x;
    const int g = blockIdx.y;
    const int b = blockIdx.z;
    const int w0 = lx * 2;
    const uint32_t ybase = smem32(yns);  // 1024-aligned

    // zero-fill pad entries (-49..-1): pad cost Σ|xn-0| emerges naturally
    if (lx < PADE)
        sts32B(ybase + swz((uint32_t)lx * 32u), 0ULL, 0ULL, 0ULL, 0ULL);

    const float2* xp = (const float2*)(x + ((b * 64 + g * CPG) * HH + h) * WW) + lx;
    const float2* yp = (const float2*)(y + ((b * 64 + g * CPG) * HH + h) * WW) + lx;

    float xv[2][CPG], yv[2][CPG];
    float sx[2] = {0.f, 0.f}, sy[2] = {0.f, 0.f};
#pragma unroll
    for (int c = 0; c < CPG; c++) {
        const float2 tx = xp[c * (CHW / 2)];
        const float2 ty = yp[c * (CHW / 2)];
        xv[0][c] = tx.x; xv[1][c] = tx.y;
        yv[0][c] = ty.x; yv[1][c] = ty.y;
        sx[0] += tx.x * tx.x; sx[1] += tx.y * tx.y;
        sy[0] += ty.x * ty.x; sy[1] += ty.y * ty.y;
    }

    u64 xn[2][4];
    u64 Wn[3][4];
#pragma unroll
    for (int p = 0; p < 2; p++) {
        const float ix =  1.f / (sqrtf(sx[p]) + EPSN);
        const float iy = -1.f / (sqrtf(sy[p]) + EPSN);   // negated: diff = add2
#pragma unroll
        for (int q = 0; q < 4; q++) {
            xn[p][q] = pack2(xv[p][2 * q] * ix, xv[p][2 * q + 1] * ix);
            Wn[p][q] = pack2(yv[p][2 * q] * iy, yv[p][2 * q + 1] * iy);
        }
    }

    // publish -yn (entry w0+p -> offset p -> slot p, matching window init)
#pragma unroll
    for (int p = 0; p < 2; p++)
        sts32B(ybase + swz((uint32_t)(w0 + p + PADE) * 32u),
               Wn[p][0], Wn[p][1], Wn[p][2], Wn[p][3]);
    __syncthreads();

    char* op = (char*)((float2*)(out + ((b * GROUP + g) * DISP * HH + h) * WW) + lx);
    uint32_t abo = ybase + (uint32_t)(w0 - 1 + PADE) * 32u;  // step-0 refill addr

    // 49 steps = 1 + 16*3, phase DM = d mod 3; offsets folded as immediates
    step<0, 0>(xn, Wn, abo, op);
    op += DSTR; abo -= 32;
#pragma unroll 2
    for (int i = 0; i < 16; i++) {
        step<1, 0>(xn, Wn, abo, op);
        step<2, 1>(xn, Wn, abo, op);
        step<0, 2>(xn, Wn, abo, op);
        op += 3 * (long long)DSTR; abo -= 96;
    }
}

extern "C" void kernel_launch(void* const* d_in, const int* in_sizes, int n_in,
                              void* d_out, int out_size) {
    const float* x = (const float*)d_in[0];
    const float* y = (const float*)d_in[1];
    float* out = (float*)d_out;

    dim3 grid(HH, GROUP, BB);   // 1536 CTAs (one per b,g,h row)
    dim3 block(160);            // 5 warps, 2 w per thread
    cost_volume_kernel<<<grid, block>>>(x, y, out);
}

// round 17
// speedup vs baseline: 1.5283x; 1.5283x over previous
#include <cuda_runtime.h>
#include <cstdint>

#define DISP 49
#define GROUP 8
#define CPG 8
#define HH 96
#define WW 320
#define BB 2
#define EPSN 1e-5f
#define CHW (HH*WW)
#define PADE 49              // zero entries for the left pad
#define ROWB 12288           // smem size: 1 KB multiple (swizzle-closed)
#define DSTR ((CHW / 2) * 8) // byte stride between disparities for one thread

typedef unsigned long long u64;

__device__ __forceinline__ uint32_t swz(uint32_t o) {
    // XOR bits[6:4] with bits[9:7]: bijective within each full 1 KB block
    return o ^ ((o >> 3) & 0x70);
}
__device__ __forceinline__ uint32_t smem32(const void* p) {
    uint32_t r;
    asm("{ .reg .u64 t; cvta.to.shared.u64 t, %1; cvt.u32.u64 %0, t; }"
        : "=r"(r) : "l"(p));
    return r;
}
__device__ __forceinline__ u64 add2(u64 a, u64 b) {
    u64 r; asm("add.rn.f32x2 %0, %1, %2;" : "=l"(r) : "l"(a), "l"(b)); return r;
}
__device__ __forceinline__ u64 pack2(float lo, float hi) {
    u64 r; asm("mov.b64 %0, {%1, %2};" : "=l"(r) : "f"(lo), "f"(hi)); return r;
}
__device__ __forceinline__ void unpack2(u64 a, float& lo, float& hi) {
    asm("mov.b64 {%0, %1}, %2;" : "=f"(lo), "=f"(hi) : "l"(a));
}
// swz(o+16) = swz(o) ^ 16 for 32-aligned o (bit 4 of o is 0; mask +16-invariant)
__device__ __forceinline__ void lds32B(u64& a, u64& b, u64& c, u64& d, uint32_t ad) {
    asm("ld.shared.v2.u64 {%0, %1}, [%2];" : "=l"(a), "=l"(b) : "r"(ad));
    asm("ld.shared.v2.u64 {%0, %1}, [%2];" : "=l"(c), "=l"(d) : "r"(ad ^ 16u));
}
__device__ __forceinline__ void sts32B(uint32_t ad, u64 a, u64 b, u64 c, u64 d) {
    asm("st.shared.v2.u64 [%0], {%1, %2};" :: "r"(ad), "l"(a), "l"(b) : "memory");
    asm("st.shared.v2.u64 [%0], {%1, %2};" :: "r"(ad ^ 16u), "l"(c), "l"(d) : "memory");
}
// streaming store: outputs are write-once, never re-read -> evict-first
__device__ __forceinline__ void stg_cs_f2(void* p, float lo, float hi) {
    asm("st.global.cs.v2.f32 [%0], {%1, %2};" :: "l"(p), "f"(lo), "f"(hi) : "memory");
}

// Pairs 0-2 abs'd via LOP3 mask, summed packed (6 add2 + 6 LOP3); pair 3
// kept raw — abs is free via FADD |.| operand modifiers in the scalar tail.
__device__ __forceinline__ float cost8(const u64 (&xp)[4], const u64 (&wp)[4]) {
    const u64 M = 0x7fffffff7fffffffULL;
    u64 d0 = add2(xp[0], wp[0]) & M;
    u64 d1 = add2(xp[1], wp[1]) & M;
    u64 d2 = add2(xp[2], wp[2]) & M;
    u64 d3 = add2(xp[3], wp[3]);
    float tl, th, dl, dh;
    unpack2(add2(add2(d0, d1), d2), tl, th);
    unpack2(d3, dl, dh);
    return (tl + th) + (fabsf(dl) + fabsf(dh));
}

// One disparity step: 2 outputs/thread. 3-slot sliding window of NEGATED yn
// entries; slot(offset o = entry - w0) = o mod 3, DM = d mod 3 compile-time.
// abo = ybase-prefolded refill address (swz(ybase+bo) = ybase+swz(bo) since
// ybase % 1024 == 0). KO folds refill/output offsets into immediates.
// Refill issued FIRST; consumed mid-NEXT-step.
template<int DM, int KO>
__device__ __forceinline__ void step(const u64 (&xn)[2][4], u64 (&Wn)[3][4],
                                     uint32_t abo, char* op) {
    constexpr int S1 = ((1 - DM) % 3 + 3) % 3;
    constexpr int S0 = ((0 - DM) % 3 + 3) % 3;
    constexpr int SR = ((-1 - DM) % 3 + 3) % 3;

    uint32_t ad = abo - 32u * KO;
    ad ^= (ad >> 3) & 0x70;
    lds32B(Wn[SR][0], Wn[SR][1], Wn[SR][2], Wn[SR][3], ad);

    const float r1 = cost8(xn[1], Wn[S1]);
    const float r0 = cost8(xn[0], Wn[S0]);
    stg_cs_f2(op + (long long)KO * DSTR, r0, r1);
}

__global__ __launch_bounds__(160, 6)
void cost_volume_kernel(const float* __restrict__ x,
                        const float* __restrict__ y,
                        float* __restrict__ out) {
    __shared__ __align__(1024) char yns[ROWB];

    const int lx = threadIdx.x;          // owns w = 2lx, 2lx+1
    const int h = blockIdx.x;
    const int g = blockIdx.y;
    const int b = blockIdx.z;
    const int w0 = lx * 2;
    const uint32_t ybase = smem32(yns);  // 1024-aligned

    // zero-fill pad entries (-49..-1): pad cost Σ|xn-0| emerges naturally
    if (lx < PADE)
        sts32B(ybase + swz((uint32_t)lx * 32u), 0ULL, 0ULL, 0ULL, 0ULL);

    const float2* xp = (const float2*)(x + ((b * 64 + g * CPG) * HH + h) * WW) + lx;
    const float2* yp = (const float2*)(y + ((b * 64 + g * CPG) * HH + h) * WW) + lx;

    float xv[2][CPG], yv[2][CPG];
    float sx[2] = {0.f, 0.f}, sy[2] = {0.f, 0.f};
#pragma unroll
    for (int c = 0; c < CPG; c++) {
        const float2 tx = xp[c * (CHW / 2)];
        const float2 ty = yp[c * (CHW / 2)];
        xv[0][c] = tx.x; xv[1][c] = tx.y;
        yv[0][c] = ty.x; yv[1][c] = ty.y;
        sx[0] += tx.x * tx.x; sx[1] += tx.y * tx.y;
        sy[0] += ty.x * ty.x; sy[1] += ty.y * ty.y;
    }

    u64 xn[2][4];
    u64 Wn[3][4];
#pragma unroll
    for (int p = 0; p < 2; p++) {
        const float ix =  1.f / (sqrtf(sx[p]) + EPSN);
        const float iy = -1.f / (sqrtf(sy[p]) + EPSN);   // negated: diff = add2
#pragma unroll
        for (int q = 0; q < 4; q++) {
            xn[p][q] = pack2(xv[p][2 * q] * ix, xv[p][2 * q + 1] * ix);
            Wn[p][q] = pack2(yv[p][2 * q] * iy, yv[p][2 * q + 1] * iy);
        }
    }

    // publish -yn (entry w0+p -> offset p -> slot p, matching window init)
#pragma unroll
    for (int p = 0; p < 2; p++)
        sts32B(ybase + swz((uint32_t)(w0 + p + PADE) * 32u),
               Wn[p][0], Wn[p][1], Wn[p][2], Wn[p][3]);
    __syncthreads();

    char* op = (char*)((float2*)(out + ((b * GROUP + g) * DISP * HH + h) * WW) + lx);
    uint32_t abo = ybase + (uint32_t)(w0 - 1 + PADE) * 32u;  // step-0 refill addr

    // 49 steps = 1 + 16*3, phase DM = d mod 3; offsets folded as immediates
    step<0, 0>(xn, Wn, abo, op);
    op += DSTR; abo -= 32;
#pragma unroll 2
    for (int i = 0; i < 16; i++) {
        step<1, 0>(xn, Wn, abo, op);
        step<2, 1>(xn, Wn, abo, op);
        step<0, 2>(xn, Wn, abo, op);
        op += 3 * (long long)DSTR; abo -= 96;
    }
}

extern "C" void kernel_launch(void* const* d_in, const int* in_sizes, int n_in,
                              void* d_out, int out_size) {
    const float* x = (const float*)d_in[0];
    const float* y = (const float*)d_in[1];
    float* out = (float*)d_out;

    dim3 grid(HH, GROUP, BB);   // 1536 CTAs (one per b,g,h row)
    dim3 block(160);            // 5 warps, 2 w per thread
    cost_volume_kernel<<<grid, block>>>(x, y, out);
}